// round 9
// baseline (speedup 1.0000x reference)
#include <cuda_runtime.h>

#define BB 8
#define SS 2048
#define HH 1024
#define NT (BB * SS)   // 16384 tokens

// Scratch (device globals — no allocation allowed in kernel_launch)
__device__ float g_ss[NT];      // score_s per token
__device__ float g_se[NT];      // score_e per token (+ bm folded in)
__device__ int   g_fl[NT];      // bit0 = start_cand, bit1 = end_cand

// ---------------------------------------------------------------------------
// Kernel 1: register-resident weights. Block = 512 threads = 16 warps =
// 2 groups of 8 warps; each group covers H=1024 (warp w owns h-slice
// [w*128,(w+1)*128), lane owns one float4). Weights folded into 16 registers
// ONCE per thread and reused for all 16 tokens of the group -> zero smem
// traffic in the main loop (was 16KB/token). Per token: 8 coalesced
// streaming LDG.128 + 16 FFMA/lane + warp shuffle-reduce; per-warp partials
// go to a 4KB smem table, combined after ONE __syncthreads.
// ---------------------------------------------------------------------------
__global__ void __launch_bounds__(512, 2)
logits_kernel(const float* __restrict__ rep,
              const int*   __restrict__ mask,
              const float* __restrict__ Ws,  const float* __restrict__ bs,
              const float* __restrict__ We,  const float* __restrict__ be,
              const float* __restrict__ Wm,  const float* __restrict__ bm)
{
    __shared__ float4 s_red[32][8];   // [token-in-block][warp-in-group]
    __shared__ float  s_bias[4];

    const int tid  = threadIdx.x;
    const int warp = tid >> 5;
    const int lane = tid & 31;
    const int g    = warp >> 3;       // group 0/1
    const int w    = warp & 7;        // warp within group

    const float wm0 = __ldg(&Wm[0]), wm1 = __ldg(&Wm[1]);
    const float wm2 = __ldg(&Wm[2]), wm3 = __ldg(&Wm[3]);

    if (tid == 0) {
        float b0 = bs[0], b1 = bs[1], c0 = be[0], c1 = be[1];
        s_bias[0] = b1 - b0;
        s_bias[1] = wm0 * b0 + wm1 * b1;
        s_bias[2] = c1 - c0;
        s_bias[3] = wm2 * c0 + wm3 * c1 + bm[0];
    }

    // ---- fold weights into registers (once) ----
    const int idx = w * 32 + lane;    // float4 h-index within token row (0..255)
    const float4* Ws4 = reinterpret_cast<const float4*>(Ws);
    const float4* We4 = reinterpret_cast<const float4*>(We);
    // Ws4[2*idx] = (Ws[4i,0],Ws[4i,1],Ws[4i+1,0],Ws[4i+1,1])
    float4 a = __ldg(&Ws4[2 * idx]);
    float4 b = __ldg(&Ws4[2 * idx + 1]);
    float4 c = __ldg(&We4[2 * idx]);
    float4 d = __ldg(&We4[2 * idx + 1]);
    const float4 wds = make_float4(a.y - a.x, a.w - a.z, b.y - b.x, b.w - b.z);
    const float4 wss = make_float4(wm0*a.x + wm1*a.y, wm0*a.z + wm1*a.w,
                                   wm0*b.x + wm1*b.y, wm0*b.z + wm1*b.w);
    const float4 wde = make_float4(c.y - c.x, c.w - c.z, d.y - d.x, d.w - d.z);
    const float4 wse = make_float4(wm2*c.x + wm3*c.y, wm2*c.z + wm3*c.w,
                                   wm2*d.x + wm3*d.y, wm2*d.z + wm3*d.w);

    // ---- main loop: 16 tokens per group ----
    const int tb = blockIdx.x * 32 + g * 16;
    const float4* rep4 = reinterpret_cast<const float4*>(rep);

    #pragma unroll 4
    for (int j = 0; j < 16; j++) {
        const int t = tb + j;
        float4 r = __ldcs(&rep4[(size_t)t * 256 + idx]);

        float ds = r.x*wds.x + r.y*wds.y + r.z*wds.z + r.w*wds.w;
        float sv = r.x*wss.x + r.y*wss.y + r.z*wss.z + r.w*wss.w;
        float de = r.x*wde.x + r.y*wde.y + r.z*wde.z + r.w*wde.w;
        float se = r.x*wse.x + r.y*wse.y + r.z*wse.z + r.w*wse.w;

        #pragma unroll
        for (int off = 16; off; off >>= 1) {
            ds += __shfl_xor_sync(0xffffffffu, ds, off);
            sv += __shfl_xor_sync(0xffffffffu, sv, off);
            de += __shfl_xor_sync(0xffffffffu, de, off);
            se += __shfl_xor_sync(0xffffffffu, se, off);
        }
        if (lane == 0)
            s_red[g * 16 + j][w] = make_float4(ds, sv, de, se);
    }
    __syncthreads();

    // ---- final combine: warps 0..7 cover 32 tokens x 8 partials ----
    if (warp < 8) {
        const int tok  = warp * 4 + (lane >> 3);  // token-in-block 0..31
        const int widx = lane & 7;
        float4 p = s_red[tok][widx];
        #pragma unroll
        for (int off = 1; off < 8; off <<= 1) {
            p.x += __shfl_xor_sync(0xffffffffu, p.x, off);
            p.y += __shfl_xor_sync(0xffffffffu, p.y, off);
            p.z += __shfl_xor_sync(0xffffffffu, p.z, off);
            p.w += __shfl_xor_sync(0xffffffffu, p.w, off);
        }
        if (widx == 0) {
            const int t = blockIdx.x * 32 + tok;
            int m  = (mask[t] != 0);
            int sc = m && ((p.x + s_bias[0]) >= 0.f);   // s0 <= s1
            int ec = m && ((p.z + s_bias[2]) >= 0.f);   // e0 <= e1
            g_ss[t] = p.y + s_bias[1];
            g_se[t] = p.w + s_bias[3];
            g_fl[t] = sc | (ec << 1);
        }
    }
}

// ---------------------------------------------------------------------------
// Kernel 2: one block per (b, i) row; 512 threads x float4 covers S=2048 cols.
// Pure HBM-write bound (268 MB) — measured at the store-path floor (~5.2TB/s)
// across every structural variant tried; keep the simplest/cheapest form.
// ---------------------------------------------------------------------------
__global__ void __launch_bounds__(512)
pair_kernel(float* __restrict__ out_valid,
            float* __restrict__ out_masked)
{
    const int i = blockIdx.x;
    const int b = blockIdx.y;
    const int t = b * SS + i;

    const float ss = g_ss[t];
    const bool  sc = (g_fl[t] & 1);

    const size_t rowoff = ((size_t)b * SS + i) * SS;
    float4* ov = reinterpret_cast<float4*>(out_valid  + rowoff);
    float4* om = reinterpret_cast<float4*>(out_masked + rowoff);

    const int j4 = threadIdx.x;        // one float4 (4 j's) per thread
    const int j0 = j4 * 4;

    float4 v, m;
    if (!sc || (j0 + 3) < i) {
        v = make_float4(0.f, 0.f, 0.f, 0.f);
        m = v;
    } else {
        const float4 se4 = reinterpret_cast<const float4*>(g_se + b * SS)[j4];
        const int4   fl4 = reinterpret_cast<const int4*>(g_fl + b * SS)[j4];

        float ps; bool val;
        ps = ss + se4.x; val = (fl4.x & 2) && (i <= j0 + 0) && (ps > 0.f);
        v.x = val ? 1.f : 0.f; m.x = val ? ps : 0.f;
        ps = ss + se4.y; val = (fl4.y & 2) && (i <= j0 + 1) && (ps > 0.f);
        v.y = val ? 1.f : 0.f; m.y = val ? ps : 0.f;
        ps = ss + se4.z; val = (fl4.z & 2) && (i <= j0 + 2) && (ps > 0.f);
        v.z = val ? 1.f : 0.f; m.z = val ? ps : 0.f;
        ps = ss + se4.w; val = (fl4.w & 2) && (i <= j0 + 3) && (ps > 0.f);
        v.w = val ? 1.f : 0.f; m.w = val ? ps : 0.f;
    }
    __stcs(ov + j4, v);
    __stcs(om + j4, m);
}

extern "C" void kernel_launch(void* const* d_in, const int* in_sizes, int n_in,
                              void* d_out, int out_size)
{
    const float* rep  = (const float*)d_in[0];
    const int*   mask = (const int*)  d_in[1];
    const float* Ws   = (const float*)d_in[2];
    const float* bs   = (const float*)d_in[3];
    const float* We   = (const float*)d_in[4];
    const float* be   = (const float*)d_in[5];
    const float* Wm   = (const float*)d_in[6];
    const float* bm   = (const float*)d_in[7];

    float* out = (float*)d_out;
    const size_t half = (size_t)BB * SS * SS;   // valid first, masked second

    logits_kernel<<<NT / 32, 512>>>(rep, mask, Ws, bs, We, be, Wm, bm);

    dim3 g2(SS, BB);
    pair_kernel<<<g2, 512>>>(out, out + half);
}

// round 10
// speedup vs baseline: 1.0308x; 1.0308x over previous
#include <cuda_runtime.h>

#define BB 8
#define SS 2048
#define HH 1024
#define NT (BB * SS)   // 16384 tokens

// Scratch (device globals — no allocation allowed in kernel_launch)
__device__ float g_ss[NT];      // score_s per token
__device__ float g_se[NT];      // score_e per token (+ bm folded in)
__device__ int   g_fl[NT];      // bit0 = start_cand, bit1 = end_cand

// ---------------------------------------------------------------------------
// Kernel 1: 512 threads = 16 warps = 16 tokens/block, 1024 blocks.
// R3-proven structure; changes vs R3: NO __ldcs on rep (plain cached loads —
// testing whether evict-first was capping the read stream at 3.6TB/s), and
// 2 float4 per lane per iter (4 iters) to double load-level parallelism.
// ---------------------------------------------------------------------------
__global__ void __launch_bounds__(512)
logits_kernel(const float* __restrict__ rep,
              const int*   __restrict__ mask,
              const float* __restrict__ Ws,  const float* __restrict__ bs,
              const float* __restrict__ We,  const float* __restrict__ be,
              const float* __restrict__ Wm,  const float* __restrict__ bm)
{
    __shared__ float s_wds[HH];   // Ws[:,1]-Ws[:,0]
    __shared__ float s_wss[HH];   // Wm0*Ws[:,0]+Wm1*Ws[:,1]
    __shared__ float s_wde[HH];   // We[:,1]-We[:,0]
    __shared__ float s_wse[HH];   // Wm2*We[:,0]+Wm3*We[:,1]
    __shared__ float s_bias[4];

    const int tid = threadIdx.x;
    {
        const float wm0 = Wm[0], wm1 = Wm[1], wm2 = Wm[2], wm3 = Wm[3];
        #pragma unroll
        for (int p = 0; p < HH / 512; p++) {
            int h = p * 512 + tid;
            float a0 = Ws[2 * h], a1 = Ws[2 * h + 1];
            float c0 = We[2 * h], c1 = We[2 * h + 1];
            s_wds[h] = a1 - a0;
            s_wss[h] = wm0 * a0 + wm1 * a1;
            s_wde[h] = c1 - c0;
            s_wse[h] = wm2 * c0 + wm3 * c1;
        }
        if (tid == 0) {
            s_bias[0] = bs[1] - bs[0];
            s_bias[1] = wm0 * bs[0] + wm1 * bs[1];
            s_bias[2] = be[1] - be[0];
            s_bias[3] = wm2 * be[0] + wm3 * be[1] + bm[0];
        }
    }
    __syncthreads();

    const int t    = blockIdx.x * 16 + (tid >> 5);   // token id
    const int lane = tid & 31;

    const float4* r4  = reinterpret_cast<const float4*>(rep + (size_t)t * HH);
    const float4* wds = reinterpret_cast<const float4*>(s_wds);
    const float4* wss = reinterpret_cast<const float4*>(s_wss);
    const float4* wde = reinterpret_cast<const float4*>(s_wde);
    const float4* wse = reinterpret_cast<const float4*>(s_wse);

    float ds = 0.f, sv = 0.f, de = 0.f, se = 0.f;
    #pragma unroll
    for (int k = 0; k < HH / 256; k++) {             // 4 iterations
        const int i0 = k * 64 + lane;
        const int i1 = i0 + 32;
        float4 r0 = r4[i0];                          // plain cached loads
        float4 r1 = r4[i1];

        float4 a0 = wds[i0], b0 = wss[i0], c0 = wde[i0], d0 = wse[i0];
        ds += r0.x*a0.x + r0.y*a0.y + r0.z*a0.z + r0.w*a0.w;
        sv += r0.x*b0.x + r0.y*b0.y + r0.z*b0.z + r0.w*b0.w;
        de += r0.x*c0.x + r0.y*c0.y + r0.z*c0.z + r0.w*c0.w;
        se += r0.x*d0.x + r0.y*d0.y + r0.z*d0.z + r0.w*d0.w;

        float4 a1 = wds[i1], b1 = wss[i1], c1 = wde[i1], d1 = wse[i1];
        ds += r1.x*a1.x + r1.y*a1.y + r1.z*a1.z + r1.w*a1.w;
        sv += r1.x*b1.x + r1.y*b1.y + r1.z*b1.z + r1.w*b1.w;
        de += r1.x*c1.x + r1.y*c1.y + r1.z*c1.z + r1.w*c1.w;
        se += r1.x*d1.x + r1.y*d1.y + r1.z*d1.z + r1.w*d1.w;
    }
    #pragma unroll
    for (int off = 16; off; off >>= 1) {
        ds += __shfl_xor_sync(0xffffffffu, ds, off);
        sv += __shfl_xor_sync(0xffffffffu, sv, off);
        de += __shfl_xor_sync(0xffffffffu, de, off);
        se += __shfl_xor_sync(0xffffffffu, se, off);
    }
    if (lane == 0) {
        int m  = (mask[t] != 0);
        int sc = m && ((ds + s_bias[0]) >= 0.f);   // s0 <= s1
        int ec = m && ((de + s_bias[2]) >= 0.f);   // e0 <= e1
        g_ss[t] = sv + s_bias[1];
        g_se[t] = se + s_bias[3];
        g_fl[t] = sc | (ec << 1);
    }
}

// ---------------------------------------------------------------------------
// Kernel 2: one block per (b, i) row; 512 threads x float4 covers S=2048 cols.
// Pure HBM-write bound (268 MB) — at the measured store floor; unchanged.
// ---------------------------------------------------------------------------
__global__ void __launch_bounds__(512)
pair_kernel(float* __restrict__ out_valid,
            float* __restrict__ out_masked)
{
    const int i = blockIdx.x;
    const int b = blockIdx.y;
    const int t = b * SS + i;

    const float ss = g_ss[t];
    const bool  sc = (g_fl[t] & 1);

    const size_t rowoff = ((size_t)b * SS + i) * SS;
    float4* ov = reinterpret_cast<float4*>(out_valid  + rowoff);
    float4* om = reinterpret_cast<float4*>(out_masked + rowoff);

    const int j4 = threadIdx.x;        // one float4 (4 j's) per thread
    const int j0 = j4 * 4;

    float4 v, m;
    if (!sc || (j0 + 3) < i) {
        v = make_float4(0.f, 0.f, 0.f, 0.f);
        m = v;
    } else {
        const float4 se4 = reinterpret_cast<const float4*>(g_se + b * SS)[j4];
        const int4   fl4 = reinterpret_cast<const int4*>(g_fl + b * SS)[j4];

        float ps; bool val;
        ps = ss + se4.x; val = (fl4.x & 2) && (i <= j0 + 0) && (ps > 0.f);
        v.x = val ? 1.f : 0.f; m.x = val ? ps : 0.f;
        ps = ss + se4.y; val = (fl4.y & 2) && (i <= j0 + 1) && (ps > 0.f);
        v.y = val ? 1.f : 0.f; m.y = val ? ps : 0.f;
        ps = ss + se4.z; val = (fl4.z & 2) && (i <= j0 + 2) && (ps > 0.f);
        v.z = val ? 1.f : 0.f; m.z = val ? ps : 0.f;
        ps = ss + se4.w; val = (fl4.w & 2) && (i <= j0 + 3) && (ps > 0.f);
        v.w = val ? 1.f : 0.f; m.w = val ? ps : 0.f;
    }
    __stcs(ov + j4, v);
    __stcs(om + j4, m);
}

extern "C" void kernel_launch(void* const* d_in, const int* in_sizes, int n_in,
                              void* d_out, int out_size)
{
    const float* rep  = (const float*)d_in[0];
    const int*   mask = (const int*)  d_in[1];
    const float* Ws   = (const float*)d_in[2];
    const float* bs   = (const float*)d_in[3];
    const float* We   = (const float*)d_in[4];
    const float* be   = (const float*)d_in[5];
    const float* Wm   = (const float*)d_in[6];
    const float* bm   = (const float*)d_in[7];

    float* out = (float*)d_out;
    const size_t half = (size_t)BB * SS * SS;   // valid first, masked second

    logits_kernel<<<NT / 16, 512>>>(rep, mask, Ws, bs, We, be, Wm, bm);

    dim3 g2(SS, BB);
    pair_kernel<<<g2, 512>>>(out, out + half);
}

// round 11
// speedup vs baseline: 1.0314x; 1.0006x over previous
#include <cuda_runtime.h>

#define BB 8
#define SS 2048
#define HH 1024
#define NT (BB * SS)   // 16384 tokens

// Scratch (device globals — no allocation allowed in kernel_launch)
// Flags are PACKED into the scores: candidate==false => score = -1e30,
// so pair_score > 0 can never fire. Saves one LDG.128 + flag ALU in pair.
__device__ float g_sse[NT];     // sc ? score_s : -1e30
__device__ float g_see[NT];     // ec ? score_e (+bm) : -1e30

#define NEGBIG (-1e30f)

// ---------------------------------------------------------------------------
// Kernel 1: exact R3-proven structure (512 thr = 16 warps = 16 tokens/block,
// 1024 blocks; smem-folded weights; 1 streaming LDG.128 + 4 LDS.128 per
// 512B of rep). Only the epilogue differs: flags packed into scores.
// ---------------------------------------------------------------------------
__global__ void __launch_bounds__(512)
logits_kernel(const float* __restrict__ rep,
              const int*   __restrict__ mask,
              const float* __restrict__ Ws,  const float* __restrict__ bs,
              const float* __restrict__ We,  const float* __restrict__ be,
              const float* __restrict__ Wm,  const float* __restrict__ bm)
{
    __shared__ float s_wds[HH];   // Ws[:,1]-Ws[:,0]
    __shared__ float s_wss[HH];   // Wm0*Ws[:,0]+Wm1*Ws[:,1]
    __shared__ float s_wde[HH];   // We[:,1]-We[:,0]
    __shared__ float s_wse[HH];   // Wm2*We[:,0]+Wm3*We[:,1]
    __shared__ float s_bias[4];

    const int tid = threadIdx.x;
    {
        const float wm0 = Wm[0], wm1 = Wm[1], wm2 = Wm[2], wm3 = Wm[3];
        #pragma unroll
        for (int p = 0; p < HH / 512; p++) {
            int h = p * 512 + tid;
            float a0 = Ws[2 * h], a1 = Ws[2 * h + 1];
            float c0 = We[2 * h], c1 = We[2 * h + 1];
            s_wds[h] = a1 - a0;
            s_wss[h] = wm0 * a0 + wm1 * a1;
            s_wde[h] = c1 - c0;
            s_wse[h] = wm2 * c0 + wm3 * c1;
        }
        if (tid == 0) {
            s_bias[0] = bs[1] - bs[0];
            s_bias[1] = wm0 * bs[0] + wm1 * bs[1];
            s_bias[2] = be[1] - be[0];
            s_bias[3] = wm2 * be[0] + wm3 * be[1] + bm[0];
        }
    }
    __syncthreads();

    const int t    = blockIdx.x * 16 + (tid >> 5);   // token id
    const int lane = tid & 31;

    const float4* r4  = reinterpret_cast<const float4*>(rep + (size_t)t * HH);
    const float4* wds = reinterpret_cast<const float4*>(s_wds);
    const float4* wss = reinterpret_cast<const float4*>(s_wss);
    const float4* wde = reinterpret_cast<const float4*>(s_wde);
    const float4* wse = reinterpret_cast<const float4*>(s_wse);

    float ds = 0.f, sv = 0.f, de = 0.f, se = 0.f;
    #pragma unroll
    for (int k = 0; k < HH / 128; k++) {
        int idx = k * 32 + lane;
        float4 r = __ldcs(&r4[idx]);         // streaming: rep is read-once
        float4 a = wds[idx];
        float4 b = wss[idx];
        float4 c = wde[idx];
        float4 d = wse[idx];
        ds += r.x*a.x + r.y*a.y + r.z*a.z + r.w*a.w;
        sv += r.x*b.x + r.y*b.y + r.z*b.z + r.w*b.w;
        de += r.x*c.x + r.y*c.y + r.z*c.z + r.w*c.w;
        se += r.x*d.x + r.y*d.y + r.z*d.z + r.w*d.w;
    }
    #pragma unroll
    for (int off = 16; off; off >>= 1) {
        ds += __shfl_xor_sync(0xffffffffu, ds, off);
        sv += __shfl_xor_sync(0xffffffffu, sv, off);
        de += __shfl_xor_sync(0xffffffffu, de, off);
        se += __shfl_xor_sync(0xffffffffu, se, off);
    }
    if (lane == 0) {
        int m  = (mask[t] != 0);
        int sc = m && ((ds + s_bias[0]) >= 0.f);   // s0 <= s1
        int ec = m && ((de + s_bias[2]) >= 0.f);   // e0 <= e1
        g_sse[t] = sc ? (sv + s_bias[1]) : NEGBIG;
        g_see[t] = ec ? (se + s_bias[3]) : NEGBIG;
    }
}

// ---------------------------------------------------------------------------
// Kernel 2: one block per (b, i) row; 512 threads x float4 covers S=2048 cols.
// Packed scores: per thread just ONE LDG.128 (se4) + block-scalar ss;
// valid = (i<=j) && (ps>0) — the -1e30 poison makes flag tests unnecessary.
// HBM-write bound (268 MB), streaming stores.
// ---------------------------------------------------------------------------
__global__ void __launch_bounds__(512)
pair_kernel(float* __restrict__ out_valid,
            float* __restrict__ out_masked)
{
    const int i = blockIdx.x;
    const int b = blockIdx.y;

    const float ss = g_sse[b * SS + i];

    const size_t rowoff = ((size_t)b * SS + i) * SS;
    float4* ov = reinterpret_cast<float4*>(out_valid  + rowoff);
    float4* om = reinterpret_cast<float4*>(out_masked + rowoff);

    const int j4 = threadIdx.x;        // one float4 (4 j's) per thread
    const int j0 = j4 * 4;

    float4 v, m;
    if (ss < -1e29f || (j0 + 3) < i) {     // row dead or fully below diagonal
        v = make_float4(0.f, 0.f, 0.f, 0.f);
        m = v;
    } else {
        const float4 se4 = reinterpret_cast<const float4*>(g_see + b * SS)[j4];

        float ps; bool val;
        ps = ss + se4.x; val = (i <= j0 + 0) && (ps > 0.f);
        v.x = val ? 1.f : 0.f; m.x = val ? ps : 0.f;
        ps = ss + se4.y; val = (i <= j0 + 1) && (ps > 0.f);
        v.y = val ? 1.f : 0.f; m.y = val ? ps : 0.f;
        ps = ss + se4.z; val = (i <= j0 + 2) && (ps > 0.f);
        v.z = val ? 1.f : 0.f; m.z = val ? ps : 0.f;
        ps = ss + se4.w; val = (i <= j0 + 3) && (ps > 0.f);
        v.w = val ? 1.f : 0.f; m.w = val ? ps : 0.f;
    }
    __stcs(ov + j4, v);
    __stcs(om + j4, m);
}

extern "C" void kernel_launch(void* const* d_in, const int* in_sizes, int n_in,
                              void* d_out, int out_size)
{
    const float* rep  = (const float*)d_in[0];
    const int*   mask = (const int*)  d_in[1];
    const float* Ws   = (const float*)d_in[2];
    const float* bs   = (const float*)d_in[3];
    const float* We   = (const float*)d_in[4];
    const float* be   = (const float*)d_in[5];
    const float* Wm   = (const float*)d_in[6];
    const float* bm   = (const float*)d_in[7];

    float* out = (float*)d_out;
    const size_t half = (size_t)BB * SS * SS;   // valid first, masked second

    logits_kernel<<<NT / 16, 512>>>(rep, mask, Ws, bs, We, be, Wm, bm);

    dim3 g2(SS, BB);
    pair_kernel<<<g2, 512>>>(out, out + half);
}